// round 3
// baseline (speedup 1.0000x reference)
#include <cuda_runtime.h>
#include <cuda_bf16.h>
#include <cstddef>

// Problem constants: B=64, S=512, D=768, max_sents=20 (id==20 discarded).
#define BB 64
#define SS 512
#define DD 768
#define MS 20
#define DC 256          // D-chunk per accum block
#define NT 64           // accum threads: each owns float4 -> 256 cols
#define NSPLIT 4
#define ROWS (SS / NSPLIT)   // 128
#define UNR 8

// Non-atomic partial sums: [NSPLIT][B][MS][D] = 15.7 MB, fully overwritten
// every call (no zeroing, no atomics, graph-deterministic).
__device__ float g_part[NSPLIT * BB * MS * DD];

// ------------------------------------------------------------- accumulate
__global__ __launch_bounds__(NT)
void accum_kernel(const float* __restrict__ hidden,
                  const int* __restrict__ sent_ids)
{
    __shared__ float acc[MS * DC];
    __shared__ int   ids[ROWS];

    const int c  = blockIdx.x;   // D-chunk (0..2)
    const int b  = blockIdx.y;   // batch
    const int sp = blockIdx.z;   // S-split (0..3)
    const int t  = threadIdx.x;
    const int s_base = sp * ROWS;
    const int col = t * 4;

    #pragma unroll
    for (int i = t; i < MS * DC; i += NT)
        acc[i] = 0.0f;

    const int* sb = sent_ids + (size_t)b * SS + s_base;
    #pragma unroll
    for (int s = t; s < ROWS; s += NT)
        ids[s] = sb[s];
    __syncthreads();

    const float* hb = hidden + (size_t)b * SS * DD + (size_t)s_base * DD
                             + (size_t)c * DC + col;

    for (int s0 = 0; s0 < ROWS; s0 += UNR) {
        float4 v[UNR];
        int    id[UNR];
        #pragma unroll
        for (int u = 0; u < UNR; u++) {
            id[u] = ids[s0 + u];
            v[u]  = *reinterpret_cast<const float4*>(hb + (size_t)(s0 + u) * DD);
        }
        #pragma unroll
        for (int u = 0; u < UNR; u++) {
            if (id[u] < MS) {
                float4* p = reinterpret_cast<float4*>(&acc[id[u] * DC + col]);
                float4 a = *p;
                a.x += v[u].x;  a.y += v[u].y;
                a.z += v[u].z;  a.w += v[u].w;
                *p = a;
            }
        }
    }
    __syncthreads();

    // flush partials: plain vector stores, unconditional (every slot written)
    float* gp = g_part + (((size_t)sp * BB + b) * MS) * DD + (size_t)c * DC + col;
    #pragma unroll
    for (int k = 0; k < MS; k++) {
        *reinterpret_cast<float4*>(gp + (size_t)k * DD) =
            *reinterpret_cast<const float4*>(&acc[k * DC + col]);
    }
}

// --------------------------------------------------------------- finalize
#define FNT 192          // 192 threads x float4 = 768 = D
#define SEG_PER_BLK 4    // 5 blocks cover MS=20 segments

__global__ __launch_bounds__(FNT)
void finalize_kernel(const float* __restrict__ hidden,
                     const int* __restrict__ sent_ids,
                     float* __restrict__ out)
{
    __shared__ int cnt[MS];
    const int b  = blockIdx.x;
    const int sc = blockIdx.y;      // segment chunk (0..4)
    const int t  = threadIdx.x;
    const int col = t * 4;

    if (t < MS) cnt[t] = 0;
    __syncthreads();

    const int* sb = sent_ids + (size_t)b * SS;
    for (int s = t; s < SS; s += FNT) {
        int id = sb[s];
        if (id < MS) atomicAdd(&cnt[id], 1);
    }
    __syncthreads();

    float* doc   = out;
    float* sreps = out + (size_t)BB * DD;

    if (sc == 0) {
        float4 v = *reinterpret_cast<const float4*>(
            hidden + (size_t)b * SS * DD + col);
        *reinterpret_cast<float4*>(doc + (size_t)b * DD + col) = v;
    }

    #pragma unroll
    for (int kk = 0; kk < SEG_PER_BLK; kk++) {
        const int k = sc * SEG_PER_BLK + kk;
        float4 s = make_float4(0.f, 0.f, 0.f, 0.f);
        #pragma unroll
        for (int sp = 0; sp < NSPLIT; sp++) {
            const float4 p = *reinterpret_cast<const float4*>(
                g_part + (((size_t)sp * BB + b) * MS + k) * DD + col);
            s.x += p.x;  s.y += p.y;  s.z += p.z;  s.w += p.w;
        }
        float inv = 1.0f / fmaxf((float)cnt[k], 1.0f);
        s.x *= inv;  s.y *= inv;  s.z *= inv;  s.w *= inv;
        *reinterpret_cast<float4*>(
            sreps + ((size_t)b * MS + k) * DD + col) = s;
    }
}

extern "C" void kernel_launch(void* const* d_in, const int* in_sizes, int n_in,
                              void* d_out, int out_size)
{
    const float* hidden   = (const float*)d_in[0];
    const int*   sent_ids = (const int*)d_in[1];
    float*       out      = (float*)d_out;

    dim3 agrid(DD / DC, BB, NSPLIT);   // (3, 64, 4) = 768 blocks
    accum_kernel<<<agrid, NT>>>(hidden, sent_ids);

    dim3 fgrid(BB, MS / SEG_PER_BLK);  // (64, 5) = 320 blocks
    finalize_kernel<<<fgrid, FNT>>>(hidden, sent_ids, out);
}

// round 4
// speedup vs baseline: 2.0551x; 2.0551x over previous
#include <cuda_runtime.h>
#include <cuda_bf16.h>
#include <cstddef>

// B=64, S=512, D=768, max_sents=20 (segment id 20 is discarded).
#define BB 64
#define SS 512
#define DD 768
#define MS 20
#define M1 21            // MS + 1
#define UNR 8

// Row buckets: for each (b, id) the list of row indices, compact per batch.
__device__ int g_rows[BB * SS];          // 128 KB
__device__ int g_cnt [BB * M1];
__device__ int g_off [BB * M1];

// ---------------------------------------------------------------- prep
// One block per batch, 512 threads (16 warps). Deterministic bucket sort of
// the 512 sent_ids via warp match + cross-warp exclusive counts.
__global__ __launch_bounds__(512)
void prep_kernel(const int* __restrict__ sent_ids)
{
    __shared__ int warp_cnt[16][32];   // [warp][id], padded
    __shared__ int cnt_s[M1];
    __shared__ int off_s[M1];

    const int b = blockIdx.x;
    const int t = threadIdx.x;
    const int w = t >> 5;
    const int l = t & 31;

    if (l < M1) warp_cnt[w][l] = 0;
    __syncwarp();

    int id = sent_ids[(size_t)b * SS + t];
    unsigned mask   = __match_any_sync(0xffffffffu, id);
    int rank_w      = __popc(mask & ((1u << l) - 1u));
    int leader      = __ffs(mask) - 1;
    if (l == leader) warp_cnt[w][id] = __popc(mask);
    __syncthreads();

    // cross-warp prefix for this thread's id
    int rank = rank_w;
    for (int w2 = 0; w2 < 16; w2++)
        if (w2 < w) rank += warp_cnt[w2][id];

    // totals per id
    if (t < M1) {
        int tot = 0;
        #pragma unroll
        for (int w2 = 0; w2 < 16; w2++) tot += warp_cnt[w2][t];
        cnt_s[t] = tot;
    }
    __syncthreads();
    if (t == 0) {
        int run = 0;
        #pragma unroll
        for (int k = 0; k < M1; k++) { off_s[k] = run; run += cnt_s[k]; }
    }
    __syncthreads();

    g_rows[(size_t)b * SS + off_s[id] + rank] = t;
    if (t < M1) {
        g_cnt[b * M1 + t] = cnt_s[t];
        g_off[b * M1 + t] = off_s[t];
    }
}

// ---------------------------------------------------------------- accum
// Block (b, k): k < 20 -> mean of rows in segment k; k == 20 -> CLS copy.
// 192 threads x float4 = 768 cols (full D per block).
#define NT 192

__global__ __launch_bounds__(NT)
void accum_kernel(const float* __restrict__ hidden,
                  float* __restrict__ out)
{
    const int b = blockIdx.x;
    const int k = blockIdx.y;
    const int col = threadIdx.x * 4;

    const float* hb = hidden + (size_t)b * SS * DD + col;

    if (k == MS) {   // doc CLS rep = hidden[b, 0, :]
        float4 v = *reinterpret_cast<const float4*>(hb);
        *reinterpret_cast<float4*>(out + (size_t)b * DD + col) = v;
        return;
    }

    __shared__ int rows_s[SS];
    const int n   = g_cnt[b * M1 + k];
    const int off = g_off[b * M1 + k];

    for (int i = threadIdx.x; i < n; i += NT)
        rows_s[i] = g_rows[(size_t)b * SS + off + i];
    __syncthreads();

    float4 a = make_float4(0.f, 0.f, 0.f, 0.f);

    int r = 0;
    for (; r + UNR <= n; r += UNR) {
        int rw[UNR];
        #pragma unroll
        for (int u = 0; u < UNR; u++) rw[u] = rows_s[r + u];
        float4 v[UNR];
        #pragma unroll
        for (int u = 0; u < UNR; u++)
            v[u] = *reinterpret_cast<const float4*>(hb + (size_t)rw[u] * DD);
        #pragma unroll
        for (int u = 0; u < UNR; u++) {
            a.x += v[u].x;  a.y += v[u].y;
            a.z += v[u].z;  a.w += v[u].w;
        }
    }
    for (; r < n; r++) {
        float4 v = *reinterpret_cast<const float4*>(hb + (size_t)rows_s[r] * DD);
        a.x += v.x;  a.y += v.y;  a.z += v.z;  a.w += v.w;
    }

    const float inv = 1.0f / fmaxf((float)n, 1.0f);
    a.x *= inv;  a.y *= inv;  a.z *= inv;  a.w *= inv;

    float* sreps = out + (size_t)BB * DD;
    *reinterpret_cast<float4*>(
        sreps + ((size_t)b * MS + k) * DD + col) = a;
}

extern "C" void kernel_launch(void* const* d_in, const int* in_sizes, int n_in,
                              void* d_out, int out_size)
{
    const float* hidden   = (const float*)d_in[0];
    const int*   sent_ids = (const int*)d_in[1];
    float*       out      = (float*)d_out;

    prep_kernel<<<BB, 512>>>(sent_ids);

    dim3 agrid(BB, M1);   // (64, 21) = 1344 blocks
    accum_kernel<<<agrid, NT>>>(hidden, out);
}

// round 5
// speedup vs baseline: 2.7851x; 1.3552x over previous
#include <cuda_runtime.h>
#include <cuda_bf16.h>
#include <cstddef>

// B=64, S=512, D=768, max_sents=20 (segment id 20 is discarded).
#define BB 64
#define SS 512
#define DD 768
#define MS 20
#define M1 21
#define UNR 8
#define NT 192    // 192 threads x float4 = 768 = D

__global__ __launch_bounds__(NT)
void fused_kernel(const float* __restrict__ hidden,
                  const int* __restrict__ sent_ids,
                  float* __restrict__ out)
{
    const int b = blockIdx.x;
    const int k = blockIdx.y;
    const int col = threadIdx.x * 4;

    const float* hb = hidden + (size_t)b * SS * DD + col;

    if (k == MS) {   // doc CLS rep = hidden[b, 0, :]
        float4 v = *reinterpret_cast<const float4*>(hb);
        *reinterpret_cast<float4*>(out + (size_t)b * DD + col) = v;
        return;
    }

    __shared__ int rows_s[SS + UNR];
    __shared__ int n_s;

    // warp 0 builds the (ascending) row list for segment k via ballot compaction
    if (threadIdx.x < 32) {
        const int l = threadIdx.x;
        const int* sb = sent_ids + (size_t)b * SS;
        int base = 0;
        #pragma unroll
        for (int c = 0; c < SS / 32; c++) {
            int row = c * 32 + l;
            int id  = sb[row];
            unsigned m = __ballot_sync(0xffffffffu, id == k);
            if (id == k)
                rows_s[base + __popc(m & ((1u << l) - 1u))] = row;
            base += __popc(m);
        }
        if (l == 0) {
            int npad = (base + UNR - 1) & ~(UNR - 1);
            for (int i = base; i < npad; i++) rows_s[i] = 0;  // pad with row 0
            n_s = base;
        }
    }
    __syncthreads();

    const int n    = n_s;
    const int npad = (n + UNR - 1) & ~(UNR - 1);

    float4 a = make_float4(0.f, 0.f, 0.f, 0.f);

    for (int r = 0; r < npad; r += UNR) {
        int rw[UNR];
        #pragma unroll
        for (int u = 0; u < UNR; u++) rw[u] = rows_s[r + u];
        float4 v[UNR];
        #pragma unroll
        for (int u = 0; u < UNR; u++)
            v[u] = *reinterpret_cast<const float4*>(hb + (size_t)rw[u] * DD);
        #pragma unroll
        for (int u = 0; u < UNR; u++) {
            a.x += v[u].x;  a.y += v[u].y;
            a.z += v[u].z;  a.w += v[u].w;
        }
    }

    // remove padding contribution (pad rows all point at row 0)
    if (npad != n) {
        float4 v0 = *reinterpret_cast<const float4*>(hb);
        float pad = (float)(npad - n);
        a.x -= pad * v0.x;  a.y -= pad * v0.y;
        a.z -= pad * v0.z;  a.w -= pad * v0.w;
    }

    const float inv = 1.0f / fmaxf((float)n, 1.0f);
    a.x *= inv;  a.y *= inv;  a.z *= inv;  a.w *= inv;

    float* sreps = out + (size_t)BB * DD;
    *reinterpret_cast<float4*>(
        sreps + ((size_t)b * MS + k) * DD + col) = a;
}

extern "C" void kernel_launch(void* const* d_in, const int* in_sizes, int n_in,
                              void* d_out, int out_size)
{
    const float* hidden   = (const float*)d_in[0];
    const int*   sent_ids = (const int*)d_in[1];
    float*       out      = (float*)d_out;

    dim3 grid(BB, M1);   // (64, 21) = 1344 blocks, single launch
    fused_kernel<<<grid, NT>>>(hidden, sent_ids, out);
}